// round 3
// baseline (speedup 1.0000x reference)
#include <cuda_runtime.h>
#include <cuda_bf16.h>

// Submanifold sparse conv, 2 layers, C=64, KV=27, N=200000, grid 128^3, B=2.
// Strategy: per-offset global pair buckets -> balanced gather-GEMM into
// partial-row scratch -> deterministic per-voxel reduce over k.

#define N_VOX   200000
#define C_CH    64
#define KV_     27
#define DD      128
#define BATCH   2
#define GRID_CELLS (BATCH * DD * DD * DD)

#define CAP_NC     16384                    // non-center bucket capacity (exp ~9300)
#define CH_CENTER  1563                     // ceil(200000/128)
#define CH_NC      128                      // ceil(CAP_NC/128)
#define TOT_ROWS   (N_VOX + 26 * CAP_NC)    // 625,984 partial rows
#define GEMM_BLOCKS (CH_CENTER + 26 * CH_NC)

__device__ int   g_grid[GRID_CELLS];
__device__ int   g_cnt[KV_];
__device__ int   g_pin[TOT_ROWS];           // in-row per bucket entry
__device__ int   g_loc[KV_ * N_VOX];        // per (k, n): bucket pos or -1
__device__ float g_part[(size_t)TOT_ROWS * C_CH];  // partial rows (~160 MB)
__device__ float g_mid[N_VOX * C_CH];

__host__ __device__ __forceinline__ int bucket_base(int k) {
    if (k == 13) return 0;
    int j = (k < 13) ? k : k - 1;
    return N_VOX + j * CAP_NC;
}

// ----------------------------------------------------------- init grid + cnt
__global__ void init_kernel() {
    int i = blockIdx.x * blockDim.x + threadIdx.x;
    int stride = gridDim.x * blockDim.x;
    int4* g4 = (int4*)g_grid;
    const int n4 = GRID_CELLS / 4;
    int4 v = make_int4(-1, -1, -1, -1);
    for (; i < n4; i += stride) g4[i] = v;
    if (blockIdx.x == 0 && threadIdx.x < KV_) g_cnt[threadIdx.x] = 0;
}

// ------------------------------------------------------------------- scatter
// Reference .at[flat].set(arange): last-index-wins = max on duplicates.
__global__ void scatter_kernel(const int* __restrict__ coors) {
    int i = blockIdx.x * blockDim.x + threadIdx.x;
    if (i >= N_VOX) return;
    int b = coors[i * 4 + 0];
    int z = coors[i * 4 + 1];
    int y = coors[i * 4 + 2];
    int x = coors[i * 4 + 3];
    int flat = ((b * DD + z) * DD + y) * DD + x;
    atomicMax(&g_grid[flat], i);
}

// -------------------------------------- fused rulebook build + k-compaction
// Warp-aggregated bucket append: one atomicAdd per warp per offset.
__global__ void build_kernel(const int* __restrict__ coors) {
    int n    = blockIdx.x * blockDim.x + threadIdx.x;
    int lane = threadIdx.x & 31;
    bool live = (n < N_VOX);
    int nn = live ? n : (N_VOX - 1);

    int b = coors[nn * 4 + 0];
    int z = coors[nn * 4 + 1];
    int y = coors[nn * 4 + 2];
    int x = coors[nn * 4 + 3];
    int base = b * DD * DD * DD;

    int k = 0;
    #pragma unroll
    for (int dz = -1; dz <= 1; dz++)
    #pragma unroll
    for (int dy = -1; dy <= 1; dy++)
    #pragma unroll
    for (int dx = -1; dx <= 1; dx++) {
        int nz = z + dz, ny = y + dy, nx = x + dx;
        int idx = -1;
        if (live && (unsigned)nz < DD && (unsigned)ny < DD && (unsigned)nx < DD)
            idx = __ldg(&g_grid[base + (nz * DD + ny) * DD + nx]);
        bool valid = (idx >= 0);
        unsigned mask = __ballot_sync(0xffffffffu, valid);
        int loc = -1;
        if (mask) {
            int leader = __ffs(mask) - 1;
            int wbase = 0;
            if (lane == leader) wbase = atomicAdd(&g_cnt[k], __popc(mask));
            wbase = __shfl_sync(0xffffffffu, wbase, leader);
            if (valid) {
                int p = wbase + __popc(mask & ((1u << lane) - 1u));
                int cap = (k == 13) ? N_VOX : CAP_NC;
                if (p < cap) {
                    g_pin[bucket_base(k) + p] = idx;
                    loc = p;
                }
            }
        }
        if (live) g_loc[k * N_VOX + n] = loc;
        k++;
    }
}

// ------------------------------------------------------- gather-GEMM per (k, chunk)
// Block: 256 thr, 128 bucket pairs of a single offset k.
// W[k] staged (16KB), features gathered (32KB). Thread owns out channels
// {2*lane, 2*lane+1}; warp processes 4 groups of 4 pairs. Plain stores to
// partial scratch (no atomics).
__global__ __launch_bounds__(256, 3)
void gemm_kernel(const float* __restrict__ fin,
                 const float* __restrict__ Wall)
{
    __shared__ float ws[C_CH * C_CH];    // 16 KB
    __shared__ float fs[128 * C_CH];     // 32 KB

    int bid = blockIdx.x;
    int k, chunk;
    if (bid < CH_CENTER) { k = 13; chunk = bid; }
    else {
        int t = bid - CH_CENTER;
        int j = t >> 7;
        chunk = t & (CH_NC - 1);
        k = (j < 13) ? j : j + 1;
    }
    int mk = g_cnt[k];
    if (k != 13 && mk > CAP_NC) mk = CAP_NC;
    int p0blk = chunk * 128;
    if (p0blk >= mk) return;
    int rem = min(128, mk - p0blk);
    int rowbase = bucket_base(k) + p0blk;

    const int tid  = threadIdx.x;
    const int lane = tid & 31;
    const int warp = tid >> 5;

    // stage W[k]
    {
        const float4* wsrc = (const float4*)(Wall + k * 4096);
        float4* wdst = (float4*)ws;
        #pragma unroll
        for (int i = 0; i < 4; i++) wdst[tid + i * 256] = wsrc[tid + i * 256];
    }
    // gather feature rows (16 threads per 256B row)
    {
        const float4* fin4 = (const float4*)fin;
        float4* fs4 = (float4*)fs;
        for (int r = tid >> 4; r < rem; r += 16)
            fs4[r * 16 + (tid & 15)] = fin4[(size_t)__ldg(&g_pin[rowbase + r]) * 16 + (tid & 15)];
    }
    __syncthreads();

    const float4* fs4 = (const float4*)fs;
    const float2* ws2 = (const float2*)ws;
    float2* part2 = (float2*)g_part;

    #pragma unroll
    for (int i = 0; i < 4; i++) {
        int g  = warp + i * 8;       // group id 0..31
        int p0 = g << 2;             // first pair of group
        if (p0 >= rem) break;

        float2 a0 = make_float2(0.f, 0.f), a1 = a0, a2 = a0, a3 = a0;
        #pragma unroll
        for (int s = 0; s < 16; s++) {
            float4 fA = fs4[(p0 + 0) * 16 + s];
            float4 fB = fs4[(p0 + 1) * 16 + s];
            float4 fC = fs4[(p0 + 2) * 16 + s];
            float4 fD = fs4[(p0 + 3) * 16 + s];
            float2 w0 = ws2[(4 * s + 0) * 32 + lane];
            float2 w1 = ws2[(4 * s + 1) * 32 + lane];
            float2 w2 = ws2[(4 * s + 2) * 32 + lane];
            float2 w3 = ws2[(4 * s + 3) * 32 + lane];

            a0.x = fmaf(fA.x, w0.x, a0.x); a0.y = fmaf(fA.x, w0.y, a0.y);
            a0.x = fmaf(fA.y, w1.x, a0.x); a0.y = fmaf(fA.y, w1.y, a0.y);
            a0.x = fmaf(fA.z, w2.x, a0.x); a0.y = fmaf(fA.z, w2.y, a0.y);
            a0.x = fmaf(fA.w, w3.x, a0.x); a0.y = fmaf(fA.w, w3.y, a0.y);

            a1.x = fmaf(fB.x, w0.x, a1.x); a1.y = fmaf(fB.x, w0.y, a1.y);
            a1.x = fmaf(fB.y, w1.x, a1.x); a1.y = fmaf(fB.y, w1.y, a1.y);
            a1.x = fmaf(fB.z, w2.x, a1.x); a1.y = fmaf(fB.z, w2.y, a1.y);
            a1.x = fmaf(fB.w, w3.x, a1.x); a1.y = fmaf(fB.w, w3.y, a1.y);

            a2.x = fmaf(fC.x, w0.x, a2.x); a2.y = fmaf(fC.x, w0.y, a2.y);
            a2.x = fmaf(fC.y, w1.x, a2.x); a2.y = fmaf(fC.y, w1.y, a2.y);
            a2.x = fmaf(fC.z, w2.x, a2.x); a2.y = fmaf(fC.z, w2.y, a2.y);
            a2.x = fmaf(fC.w, w3.x, a2.x); a2.y = fmaf(fC.w, w3.y, a2.y);

            a3.x = fmaf(fD.x, w0.x, a3.x); a3.y = fmaf(fD.x, w0.y, a3.y);
            a3.x = fmaf(fD.y, w1.x, a3.x); a3.y = fmaf(fD.y, w1.y, a3.y);
            a3.x = fmaf(fD.z, w2.x, a3.x); a3.y = fmaf(fD.z, w2.y, a3.y);
            a3.x = fmaf(fD.w, w3.x, a3.x); a3.y = fmaf(fD.w, w3.y, a3.y);
        }
        if (p0 + 0 < rem) part2[(size_t)(rowbase + p0 + 0) * 32 + lane] = a0;
        if (p0 + 1 < rem) part2[(size_t)(rowbase + p0 + 1) * 32 + lane] = a1;
        if (p0 + 2 < rem) part2[(size_t)(rowbase + p0 + 2) * 32 + lane] = a2;
        if (p0 + 3 < rem) part2[(size_t)(rowbase + p0 + 3) * 32 + lane] = a3;
    }
}

// -------------------------------------------------- reduce: sum partials over k
// One warp per output voxel; fixed k order -> deterministic fp summation.
__global__ __launch_bounds__(256)
void reduce_kernel(float* __restrict__ fout)
{
    int warp = threadIdx.x >> 5;
    int lane = threadIdx.x & 31;
    int n = blockIdx.x * 8 + warp;
    if (n >= N_VOX) return;

    const float2* part2 = (const float2*)g_part;
    float2 acc = make_float2(0.f, 0.f);
    #pragma unroll
    for (int k = 0; k < KV_; k++) {
        int loc = __ldg(&g_loc[k * N_VOX + n]);
        if (loc >= 0) {
            float2 v = part2[(size_t)(bucket_base(k) + loc) * 32 + lane];
            acc.x += v.x; acc.y += v.y;
        }
    }
    ((float2*)fout)[(size_t)n * 32 + lane] = acc;
}

// -------------------------------------------------------------------- launch
extern "C" void kernel_launch(void* const* d_in, const int* in_sizes, int n_in,
                              void* d_out, int out_size)
{
    const float* feats = (const float*)d_in[0];
    const int*   coors = (const int*)d_in[1];
    const float* W0    = (const float*)d_in[2];
    const float* W1    = (const float*)d_in[3];
    float*       out   = (float*)d_out;

    init_kernel<<<1024, 256>>>();
    scatter_kernel<<<(N_VOX + 255) / 256, 256>>>(coors);
    build_kernel<<<(N_VOX + 255) / 256, 256>>>(coors);

    gemm_kernel<<<GEMM_BLOCKS, 256>>>(feats, W0);
    reduce_kernel<<<(N_VOX + 7) / 8, 256>>>(g_mid);

    gemm_kernel<<<GEMM_BLOCKS, 256>>>(g_mid, W1);
    reduce_kernel<<<(N_VOX + 7) / 8, 256>>>(out);
}

// round 5
// speedup vs baseline: 4.7236x; 4.7236x over previous
#include <cuda_runtime.h>
#include <cuda_bf16.h>

// Submanifold sparse conv, 2 layers, C=64, KV=27, N=200000, grid 128^3, B=2.
// Per-offset global pair buckets -> balanced gather-GEMM that accumulates
// directly into the output rows via red.global.add.v4.f32 (no partials).

#define N_VOX   200000
#define C_CH    64
#define KV_     27
#define DD      128
#define BATCH   2
#define GRID_CELLS (BATCH * DD * DD * DD)

#define CAP_NC     16384                    // non-center bucket cap (exp ~9500)
#define CH_CENTER  1563                     // ceil(200000/128)
#define CH_NC      128                      // ceil(CAP_NC/128)
#define TOT_ROWS   (N_VOX + 26 * CAP_NC)
#define GEMM_BLOCKS (CH_CENTER + 26 * CH_NC)

__device__ int   g_grid[GRID_CELLS];
__device__ int   g_cnt[KV_];
__device__ int   g_pin[TOT_ROWS];           // input row per pair
__device__ int   g_pout[TOT_ROWS];          // output row per pair
__device__ float g_mid[(size_t)N_VOX * C_CH];

__host__ __device__ __forceinline__ int bucket_base(int k) {
    if (k == 13) return 0;
    int j = (k < 13) ? k : k - 1;
    return N_VOX + j * CAP_NC;
}

// ----------------------------------------------------------- init grid + cnt
__global__ void init_kernel() {
    int i = blockIdx.x * blockDim.x + threadIdx.x;
    int stride = gridDim.x * blockDim.x;
    int4* g4 = (int4*)g_grid;
    const int n4 = GRID_CELLS / 4;
    int4 v = make_int4(-1, -1, -1, -1);
    for (; i < n4; i += stride) g4[i] = v;
    if (blockIdx.x == 0 && threadIdx.x < KV_) g_cnt[threadIdx.x] = 0;
}

// ------------------------------------------------------------------- zero
__global__ void zero_kernel(float* __restrict__ p) {
    const int n4 = N_VOX * C_CH / 4;
    float4* p4 = (float4*)p;
    float4 z = make_float4(0.f, 0.f, 0.f, 0.f);
    for (int i = blockIdx.x * blockDim.x + threadIdx.x; i < n4;
         i += gridDim.x * blockDim.x)
        p4[i] = z;
}

// ------------------------------------------------------------------- scatter
// Reference .at[flat].set(arange): last-index-wins = max on duplicates.
__global__ void scatter_kernel(const int* __restrict__ coors) {
    int i = blockIdx.x * blockDim.x + threadIdx.x;
    if (i >= N_VOX) return;
    int4 c = ((const int4*)coors)[i];
    int flat = ((c.x * DD + c.y) * DD + c.z) * DD + c.w;
    atomicMax(&g_grid[flat], i);
}

// -------------------------------------- fused rulebook build + k-compaction
__global__ void build_kernel(const int* __restrict__ coors) {
    int n    = blockIdx.x * blockDim.x + threadIdx.x;
    int lane = threadIdx.x & 31;
    bool live = (n < N_VOX);
    int4 c = ((const int4*)coors)[live ? n : (N_VOX - 1)];
    int base = c.x * DD * DD * DD;

    int k = 0;
    #pragma unroll
    for (int dz = -1; dz <= 1; dz++)
    #pragma unroll
    for (int dy = -1; dy <= 1; dy++)
    #pragma unroll
    for (int dx = -1; dx <= 1; dx++) {
        int nz = c.y + dz, ny = c.z + dy, nx = c.w + dx;
        int idx = -1;
        if (live && (unsigned)nz < DD && (unsigned)ny < DD && (unsigned)nx < DD)
            idx = __ldg(&g_grid[base + (nz * DD + ny) * DD + nx]);
        bool valid = (idx >= 0);
        unsigned mask = __ballot_sync(0xffffffffu, valid);
        if (mask) {
            int leader = __ffs(mask) - 1;
            int wbase = 0;
            if (lane == leader) wbase = atomicAdd(&g_cnt[k], __popc(mask));
            wbase = __shfl_sync(0xffffffffu, wbase, leader);
            if (valid) {
                int p = wbase + __popc(mask & ((1u << lane) - 1u));
                int cap = (k == 13) ? N_VOX : CAP_NC;
                if (p < cap) {
                    int bb = bucket_base(k);
                    g_pin[bb + p]  = idx;
                    g_pout[bb + p] = n;
                }
            }
        }
        k++;
    }
}

// --------------------------------------------------- gather-GEMM + RED output
// Block: 256 thr, one (k, 128-pair chunk). Stage W[k] row-major [c][o] (16KB),
// gather 128 feature rows (32KB). Warp group = 8 pairs: lane -> subpair
// (lane>>4) and 4 consecutive out channels (4*(lane&15)). Per 4-channel step:
// 8 LDS.128 + 64 FMA per thread (1.125 instr/FMA). Each accumulator flushes
// with one red.global.add.v4.f32.
__device__ __forceinline__ void fma4(float4& acc, float s, const float4& wv) {
    acc.x = fmaf(s, wv.x, acc.x);
    acc.y = fmaf(s, wv.y, acc.y);
    acc.z = fmaf(s, wv.z, acc.z);
    acc.w = fmaf(s, wv.w, acc.w);
}

__device__ __forceinline__ void red_v4(float* ptr, float4 v) {
    asm volatile("red.global.add.v4.f32 [%0], {%1, %2, %3, %4};"
                 :: "l"(ptr), "f"(v.x), "f"(v.y), "f"(v.z), "f"(v.w)
                 : "memory");
}

__global__ __launch_bounds__(256, 3)
void gemm_kernel(const float* __restrict__ fin,
                 const float* __restrict__ Wall,
                 float* __restrict__ fout)
{
    __shared__ float ws[C_CH * C_CH];    // 16 KB
    __shared__ float fs[128 * C_CH];     // 32 KB
    __shared__ int   spo[128];

    int bid = blockIdx.x;
    int k, chunk;
    if (bid < CH_CENTER) { k = 13; chunk = bid; }
    else {
        int t = bid - CH_CENTER;
        int j = t >> 7;
        chunk = t & (CH_NC - 1);
        k = (j < 13) ? j : j + 1;
    }
    int mk = g_cnt[k];
    if (k != 13 && mk > CAP_NC) mk = CAP_NC;
    int p0blk = chunk * 128;
    if (p0blk >= mk) return;
    int rem = min(128, mk - p0blk);
    int rowbase = bucket_base(k) + p0blk;

    const int tid  = threadIdx.x;
    const int lane = tid & 31;
    const int warp = tid >> 5;

    // stage W[k] row-major [c][o]
    {
        const float4* wsrc = (const float4*)(Wall + k * 4096);
        float4* wdst = (float4*)ws;
        #pragma unroll
        for (int i = 0; i < 4; i++) wdst[tid + i * 256] = wsrc[tid + i * 256];
    }
    // stage out rows + gather feature rows (16 threads per 256B row)
    if (tid < 128 && tid < rem) spo[tid] = __ldg(&g_pout[rowbase + tid]);
    {
        const float4* fin4 = (const float4*)fin;
        float4* fs4 = (float4*)fs;
        for (int r = tid >> 4; r < rem; r += 16)
            fs4[r * 16 + (tid & 15)] =
                fin4[(size_t)__ldg(&g_pin[rowbase + r]) * 16 + (tid & 15)];
    }
    __syncthreads();

    const float4* fsv = (const float4*)fs;
    const float4* wsv = (const float4*)ws;
    const int sub = lane >> 4;        // 0/1 : which 4-pair subgroup
    const int oc4 = lane & 15;        // out-channel block (4 ch)

    const int ngroups = (rem + 7) >> 3;
    for (int g = warp; g < ngroups; g += 8) {
        const int pb = g * 8 + sub * 4;
        const int q0 = min(pb + 0, rem - 1);
        const int q1 = min(pb + 1, rem - 1);
        const int q2 = min(pb + 2, rem - 1);
        const int q3 = min(pb + 3, rem - 1);

        float4 a0 = make_float4(0.f, 0.f, 0.f, 0.f), a1 = a0, a2 = a0, a3 = a0;

        #pragma unroll 4
        for (int c4 = 0; c4 < 16; c4++) {
            float4 f0 = fsv[q0 * 16 + c4];
            float4 f1 = fsv[q1 * 16 + c4];
            float4 f2 = fsv[q2 * 16 + c4];
            float4 f3 = fsv[q3 * 16 + c4];
            float4 w0 = wsv[(4 * c4 + 0) * 16 + oc4];
            float4 w1 = wsv[(4 * c4 + 1) * 16 + oc4];
            float4 w2 = wsv[(4 * c4 + 2) * 16 + oc4];
            float4 w3 = wsv[(4 * c4 + 3) * 16 + oc4];

            fma4(a0, f0.x, w0); fma4(a0, f0.y, w1); fma4(a0, f0.z, w2); fma4(a0, f0.w, w3);
            fma4(a1, f1.x, w0); fma4(a1, f1.y, w1); fma4(a1, f1.z, w2); fma4(a1, f1.w, w3);
            fma4(a2, f2.x, w0); fma4(a2, f2.y, w1); fma4(a2, f2.z, w2); fma4(a2, f2.w, w3);
            fma4(a3, f3.x, w0); fma4(a3, f3.y, w1); fma4(a3, f3.z, w2); fma4(a3, f3.w, w3);
        }

        if (pb + 0 < rem) red_v4(fout + (size_t)spo[pb + 0] * C_CH + oc4 * 4, a0);
        if (pb + 1 < rem) red_v4(fout + (size_t)spo[pb + 1] * C_CH + oc4 * 4, a1);
        if (pb + 2 < rem) red_v4(fout + (size_t)spo[pb + 2] * C_CH + oc4 * 4, a2);
        if (pb + 3 < rem) red_v4(fout + (size_t)spo[pb + 3] * C_CH + oc4 * 4, a3);
    }
}

// -------------------------------------------------------------------- launch
extern "C" void kernel_launch(void* const* d_in, const int* in_sizes, int n_in,
                              void* d_out, int out_size)
{
    const float* feats = (const float*)d_in[0];
    const int*   coors = (const int*)d_in[1];
    const float* W0    = (const float*)d_in[2];
    const float* W1    = (const float*)d_in[3];
    float*       out   = (float*)d_out;

    float* mid;
    cudaGetSymbolAddress((void**)&mid, g_mid);

    init_kernel<<<1024, 256>>>();
    scatter_kernel<<<(N_VOX + 255) / 256, 256>>>(coors);
    build_kernel<<<(N_VOX + 255) / 256, 256>>>(coors);

    zero_kernel<<<2048, 256>>>(mid);
    gemm_kernel<<<GEMM_BLOCKS, 256>>>(feats, W0, mid);

    zero_kernel<<<2048, 256>>>(out);
    gemm_kernel<<<GEMM_BLOCKS, 256>>>(mid, W1, out);
}

// round 6
// speedup vs baseline: 4.8151x; 1.0194x over previous
#include <cuda_runtime.h>
#include <cuda_bf16.h>

// Submanifold sparse conv, 2 layers, C=64, KV=27, N=200000, grid 128^3, B=2.
// Per-offset global pair buckets -> balanced gather-GEMM with packed f32x2
// FFMA2 math, accumulating into output rows via red.global.add.v4.f32.

#define N_VOX   200000
#define C_CH    64
#define KV_     27
#define DD      128
#define BATCH   2
#define GRID_CELLS (BATCH * DD * DD * DD)

#define CAP_NC     16384                    // non-center bucket cap (exp ~9500)
#define CH_CENTER  1563                     // ceil(200000/128)
#define CH_NC      128                      // ceil(CAP_NC/128)
#define TOT_ROWS   (N_VOX + 26 * CAP_NC)
#define GEMM_BLOCKS (CH_CENTER + 26 * CH_NC)

__device__ int   g_grid[GRID_CELLS];
__device__ int   g_cnt[KV_];
__device__ int   g_pin[TOT_ROWS];           // input row per pair
__device__ int   g_pout[TOT_ROWS];          // output row per pair
__device__ float g_mid[(size_t)N_VOX * C_CH];

__host__ __device__ __forceinline__ int bucket_base(int k) {
    if (k == 13) return 0;
    int j = (k < 13) ? k : k - 1;
    return N_VOX + j * CAP_NC;
}

// ------------------------- init: grid=-1, cnt=0, zero mid and out ----------
__global__ void init_kernel(float* __restrict__ out) {
    int tid0 = blockIdx.x * blockDim.x + threadIdx.x;
    int stride = gridDim.x * blockDim.x;

    int4* g4 = (int4*)g_grid;
    const int ng4 = GRID_CELLS / 4;
    int4 mone = make_int4(-1, -1, -1, -1);
    for (int i = tid0; i < ng4; i += stride) g4[i] = mone;

    const int nf4 = N_VOX * C_CH / 4;
    float4 z = make_float4(0.f, 0.f, 0.f, 0.f);
    float4* m4 = (float4*)g_mid;
    float4* o4 = (float4*)out;
    for (int i = tid0; i < nf4; i += stride) { m4[i] = z; o4[i] = z; }

    if (blockIdx.x == 0 && threadIdx.x < KV_) g_cnt[threadIdx.x] = 0;
}

// ------------------------------------------------------------------- scatter
// Reference .at[flat].set(arange): last-index-wins = max on duplicates.
__global__ void scatter_kernel(const int* __restrict__ coors) {
    int i = blockIdx.x * blockDim.x + threadIdx.x;
    if (i >= N_VOX) return;
    int4 c = ((const int4*)coors)[i];
    int flat = ((c.x * DD + c.y) * DD + c.z) * DD + c.w;
    atomicMax(&g_grid[flat], i);
}

// -------------------------------------- fused rulebook build + k-compaction
__global__ void build_kernel(const int* __restrict__ coors) {
    int n    = blockIdx.x * blockDim.x + threadIdx.x;
    int lane = threadIdx.x & 31;
    bool live = (n < N_VOX);
    int4 c = ((const int4*)coors)[live ? n : (N_VOX - 1)];
    int base = c.x * DD * DD * DD;

    int k = 0;
    #pragma unroll
    for (int dz = -1; dz <= 1; dz++)
    #pragma unroll
    for (int dy = -1; dy <= 1; dy++)
    #pragma unroll
    for (int dx = -1; dx <= 1; dx++) {
        int nz = c.y + dz, ny = c.z + dy, nx = c.w + dx;
        int idx = -1;
        if (live && (unsigned)nz < DD && (unsigned)ny < DD && (unsigned)nx < DD)
            idx = __ldg(&g_grid[base + (nz * DD + ny) * DD + nx]);
        bool valid = (idx >= 0);
        unsigned mask = __ballot_sync(0xffffffffu, valid);
        if (mask) {
            int leader = __ffs(mask) - 1;
            int wbase = 0;
            if (lane == leader) wbase = atomicAdd(&g_cnt[k], __popc(mask));
            wbase = __shfl_sync(0xffffffffu, wbase, leader);
            if (valid) {
                int p = wbase + __popc(mask & ((1u << lane) - 1u));
                int cap = (k == 13) ? N_VOX : CAP_NC;
                if (p < cap) {
                    int bb = bucket_base(k);
                    g_pin[bb + p]  = idx;
                    g_pout[bb + p] = n;
                }
            }
        }
        k++;
    }
}

// ----------------------------------------------- packed f32x2 FMA helpers
typedef unsigned long long u64t;

__device__ __forceinline__ u64t pack2(float s) {
    u64t r;
    asm("mov.b64 %0, {%1, %1};" : "=l"(r) : "f"(s));
    return r;
}
__device__ __forceinline__ void ffma2(u64t& d, u64t a, u64t b) {
    asm("fma.rn.f32x2 %0, %1, %2, %0;" : "+l"(d) : "l"(a), "l"(b));
}
__device__ __forceinline__ void red_v4(float* ptr, u64t lo, u64t hi) {
    float x, y, z, w;
    asm("mov.b64 {%0, %1}, %2;" : "=f"(x), "=f"(y) : "l"(lo));
    asm("mov.b64 {%0, %1}, %2;" : "=f"(z), "=f"(w) : "l"(hi));
    asm volatile("red.global.add.v4.f32 [%0], {%1, %2, %3, %4};"
                 :: "l"(ptr), "f"(x), "f"(y), "f"(z), "f"(w)
                 : "memory");
}

// --------------------------------------------------- gather-GEMM + RED output
// Block: 256 thr, one (k, 128-pair chunk). W[k] staged row-major [c][o] (16KB),
// 128 feature rows gathered (32KB). Warp group = 8 pairs: lane -> subpair
// (lane>>4, 4 pairs each) x out-channel block oc4 = lane&15 (4 channels).
// Inner step (4 input channels): 8 LDS.128 + 16 packs + 32 FFMA2 per thread
// = 56 instr / 64 FMA. Accumulators are packed f32x2; flush via RED.v4.
__global__ __launch_bounds__(256, 3)
void gemm_kernel(const float* __restrict__ fin,
                 const float* __restrict__ Wall,
                 float* __restrict__ fout)
{
    __shared__ float ws[C_CH * C_CH];    // 16 KB
    __shared__ float fs[128 * C_CH];     // 32 KB
    __shared__ int   spo[128];

    int bid = blockIdx.x;
    int k, chunk;
    if (bid < CH_CENTER) { k = 13; chunk = bid; }
    else {
        int t = bid - CH_CENTER;
        int j = t >> 7;
        chunk = t & (CH_NC - 1);
        k = (j < 13) ? j : j + 1;
    }
    int mk = g_cnt[k];
    if (k != 13 && mk > CAP_NC) mk = CAP_NC;
    int p0blk = chunk * 128;
    if (p0blk >= mk) return;
    int rem = min(128, mk - p0blk);
    int rowbase = bucket_base(k) + p0blk;

    const int tid  = threadIdx.x;
    const int lane = tid & 31;
    const int warp = tid >> 5;

    // stage W[k] row-major [c][o]
    {
        const float4* wsrc = (const float4*)(Wall + k * 4096);
        float4* wdst = (float4*)ws;
        #pragma unroll
        for (int i = 0; i < 4; i++) wdst[tid + i * 256] = wsrc[tid + i * 256];
    }
    // stage out rows + gather feature rows (16 threads per 256B row)
    if (tid < 128 && tid < rem) spo[tid] = __ldg(&g_pout[rowbase + tid]);
    {
        const float4* fin4 = (const float4*)fin;
        float4* fs4 = (float4*)fs;
        for (int r = tid >> 4; r < rem; r += 16)
            fs4[r * 16 + (tid & 15)] =
                fin4[(size_t)__ldg(&g_pin[rowbase + r]) * 16 + (tid & 15)];
    }
    __syncthreads();

    const float4*      fsv = (const float4*)fs;
    const ulonglong2*  ws8 = (const ulonglong2*)ws;   // [c][oc4]: .x=ch01 .y=ch23
    const int sub = lane >> 4;        // 0/1 : which 4-pair subgroup
    const int oc4 = lane & 15;        // out-channel block (4 ch)

    const int ngroups = (rem + 7) >> 3;
    for (int g = warp; g < ngroups; g += 8) {
        const int pb = g * 8 + sub * 4;
        const int q0 = min(pb + 0, rem - 1);
        const int q1 = min(pb + 1, rem - 1);
        const int q2 = min(pb + 2, rem - 1);
        const int q3 = min(pb + 3, rem - 1);

        u64t a0l = 0, a0h = 0, a1l = 0, a1h = 0;
        u64t a2l = 0, a2h = 0, a3l = 0, a3h = 0;

        #pragma unroll 4
        for (int c4 = 0; c4 < 16; c4++) {
            float4 f0 = fsv[q0 * 16 + c4];
            float4 f1 = fsv[q1 * 16 + c4];
            float4 f2 = fsv[q2 * 16 + c4];
            float4 f3 = fsv[q3 * 16 + c4];
            ulonglong2 w0 = ws8[(4 * c4 + 0) * 16 + oc4];
            ulonglong2 w1 = ws8[(4 * c4 + 1) * 16 + oc4];
            ulonglong2 w2 = ws8[(4 * c4 + 2) * 16 + oc4];
            ulonglong2 w3 = ws8[(4 * c4 + 3) * 16 + oc4];

            u64t s;
            s = pack2(f0.x); ffma2(a0l, s, w0.x); ffma2(a0h, s, w0.y);
            s = pack2(f0.y); ffma2(a0l, s, w1.x); ffma2(a0h, s, w1.y);
            s = pack2(f0.z); ffma2(a0l, s, w2.x); ffma2(a0h, s, w2.y);
            s = pack2(f0.w); ffma2(a0l, s, w3.x); ffma2(a0h, s, w3.y);

            s = pack2(f1.x); ffma2(a1l, s, w0.x); ffma2(a1h, s, w0.y);
            s = pack2(f1.y); ffma2(a1l, s, w1.x); ffma2(a1h, s, w1.y);
            s = pack2(f1.z); ffma2(a1l, s, w2.x); ffma2(a1h, s, w2.y);
            s = pack2(f1.w); ffma2(a1l, s, w3.x); ffma2(a1h, s, w3.y);

            s = pack2(f2.x); ffma2(a2l, s, w0.x); ffma2(a2h, s, w0.y);
            s = pack2(f2.y); ffma2(a2l, s, w1.x); ffma2(a2h, s, w1.y);
            s = pack2(f2.z); ffma2(a2l, s, w2.x); ffma2(a2h, s, w2.y);
            s = pack2(f2.w); ffma2(a2l, s, w3.x); ffma2(a2h, s, w3.y);

            s = pack2(f3.x); ffma2(a3l, s, w0.x); ffma2(a3h, s, w0.y);
            s = pack2(f3.y); ffma2(a3l, s, w1.x); ffma2(a3h, s, w1.y);
            s = pack2(f3.z); ffma2(a3l, s, w2.x); ffma2(a3h, s, w2.y);
            s = pack2(f3.w); ffma2(a3l, s, w3.x); ffma2(a3h, s, w3.y);
        }

        if (pb + 0 < rem) red_v4(fout + (size_t)spo[pb + 0] * C_CH + oc4 * 4, a0l, a0h);
        if (pb + 1 < rem) red_v4(fout + (size_t)spo[pb + 1] * C_CH + oc4 * 4, a1l, a1h);
        if (pb + 2 < rem) red_v4(fout + (size_t)spo[pb + 2] * C_CH + oc4 * 4, a2l, a2h);
        if (pb + 3 < rem) red_v4(fout + (size_t)spo[pb + 3] * C_CH + oc4 * 4, a3l, a3h);
    }
}

// -------------------------------------------------------------------- launch
extern "C" void kernel_launch(void* const* d_in, const int* in_sizes, int n_in,
                              void* d_out, int out_size)
{
    const float* feats = (const float*)d_in[0];
    const int*   coors = (const int*)d_in[1];
    const float* W0    = (const float*)d_in[2];
    const float* W1    = (const float*)d_in[3];
    float*       out   = (float*)d_out;

    float* mid;
    cudaGetSymbolAddress((void**)&mid, g_mid);

    init_kernel<<<2048, 256>>>(out);
    scatter_kernel<<<(N_VOX + 255) / 256, 256>>>(coors);
    build_kernel<<<(N_VOX + 255) / 256, 256>>>(coors);

    gemm_kernel<<<GEMM_BLOCKS, 256>>>(feats, W0, mid);
    gemm_kernel<<<GEMM_BLOCKS, 256>>>(mid, W1, out);
}